// round 16
// baseline (speedup 1.0000x reference)
#include <cuda_runtime.h>
#include <cuda_fp16.h>
#include <cstdint>

// Problem constants
#define DIMD 256
#define KAT  512
#define NCOL 65536
#define NB   64          // prep CTAs (barrier group) — prep is now NS-only
#define NDUAL 6          // dual Newton-Schulz passes (then one final Y-only pass)

// Chebyshev degree-1 start for Newton-Schulz (residual 0.865 on [30,1600])
#define A_COEF 4.57720e-3f
#define B_COEF (-2.80809e-6f)
#define NODIAG (-1000000)

// ---------------------------------------------------------------------------
// Device scratch (no allocations allowed)
// ---------------------------------------------------------------------------
__device__ float g_G[DIMD * DIMD];
__device__ float g_Y[2 * DIMD * DIMD];    // Y ping-pong
__device__ float g_Z[2 * DIMD * DIMD];    // Z = G*Y ping-pong
__device__ unsigned g_bar = 0;            // monotone grid barrier

// B images only (W): per (img = kh*4+chunk, 8 imgs): [split 2][256 k][64 d]
__device__ __align__(1024) __half g_Bimg[8 * 2 * 16384];        // 512 KB

// ---------------------------------------------------------------------------
// PTX helpers (portable PTX only — no 'a'-suffix features)
// ---------------------------------------------------------------------------
__device__ __forceinline__ uint32_t smem_u32(const void* p) {
    uint32_t a;
    asm("{ .reg .u64 tmp; cvta.to.shared.u64 tmp, %1; cvt.u32.u64 %0, tmp; }"
        : "=r"(a) : "l"(p));
    return a;
}

#define MBARRIER_INIT(addr, cnt) \
    asm volatile("mbarrier.init.shared.b64 [%0], %1;" :: "r"(addr), "r"(cnt) : "memory")
#define MBARRIER_EXPECT_TX(addr, bytes) \
    asm volatile("mbarrier.arrive.expect_tx.shared.b64 _, [%0], %1;" \
                 :: "r"(addr), "r"(bytes) : "memory")
#define MBARRIER_ARRIVE(addr) \
    asm volatile("mbarrier.arrive.shared.b64 _, [%0];" :: "r"(addr) : "memory")

#define MBARRIER_WAIT_PARITY(addr, par) do {                                   \
    uint32_t _m = (addr), _p = (par), _done;                                   \
    asm volatile("{\n\t.reg .pred p;\n\t"                                      \
        "mbarrier.try_wait.parity.acquire.cta.shared::cta.b64 p, [%1], %2;\n\t"\
        "selp.b32 %0, 1, 0, p;\n\t}"                                           \
        : "=r"(_done) : "r"(_m), "r"(_p) : "memory");                          \
    if (!_done) {                                                              \
        asm volatile("{\n\t.reg .pred P1;\n\t"                                 \
            "WL_%=:\n\t"                                                       \
            "mbarrier.try_wait.parity.acquire.cta.shared::cta.b64 P1, [%0], %1, 0x989680;\n\t" \
            "@P1 bra.uni WD_%=;\n\t"                                           \
            "bra.uni WL_%=;\n\t"                                               \
            "WD_%=:\n\t}"                                                      \
            :: "r"(_m), "r"(_p) : "memory");                                   \
    }                                                                          \
} while (0)

__device__ __forceinline__ void bulk_g2s(uint32_t dst, const void* src,
                                         uint32_t bytes, uint32_t mbar) {
    asm volatile("cp.async.bulk.shared::cta.global.mbarrier::complete_tx::bytes "
                 "[%0], [%1], %2, [%3];"
                 :: "r"(dst), "l"(src), "r"(bytes), "r"(mbar) : "memory");
}

#define LDSM_X4(r0, r1, r2, r3, a) \
    asm volatile("ldmatrix.sync.aligned.m8n8.x4.shared.b16 {%0,%1,%2,%3}, [%4];" \
        : "=r"(r0), "=r"(r1), "=r"(r2), "=r"(r3) : "r"(a))
#define LDSM_X4T(r0, r1, r2, r3, a) \
    asm volatile("ldmatrix.sync.aligned.m8n8.x4.trans.shared.b16 {%0,%1,%2,%3}, [%4];" \
        : "=r"(r0), "=r"(r1), "=r"(r2), "=r"(r3) : "r"(a))
#define LDSM_X2(r0, r1, a) \
    asm volatile("ldmatrix.sync.aligned.m8n8.x2.shared.b16 {%0,%1}, [%2];" \
        : "=r"(r0), "=r"(r1) : "r"(a))
#define STS128(a, r0, r1, r2, r3) \
    asm volatile("st.shared.v4.b32 [%0], {%1,%2,%3,%4};" \
        :: "r"(a), "r"(r0), "r"(r1), "r"(r2), "r"(r3) : "memory")

#define MMA_F16(d0, d1, d2, d3, a0, a1, a2, a3, b0, b1) \
    asm volatile("mma.sync.aligned.m16n8k16.row.col.f32.f16.f16.f32 " \
        "{%0,%1,%2,%3}, {%4,%5,%6,%7}, {%8,%9}, {%0,%1,%2,%3};" \
        : "+f"(d0), "+f"(d1), "+f"(d2), "+f"(d3) \
        : "r"(a0), "r"(a1), "r"(a2), "r"(a3), "r"(b0), "r"(b1))

__device__ __forceinline__ unsigned short hbits(__half h) {
    return *reinterpret_cast<unsigned short*>(&h);
}

// pack two floats into one fp16x2 hi word + one fp16x2 lo word
__device__ __forceinline__ void split2(float v0, float v1, unsigned& uh, unsigned& ul) {
    __half h0 = __float2half_rn(v0);
    __half h1 = __float2half_rn(v1);
    __half l0 = __float2half_rn(v0 - __half2float(h0));
    __half l1 = __float2half_rn(v1 - __half2float(h1));
    uh = (unsigned)hbits(h0) | ((unsigned)hbits(h1) << 16);
    ul = (unsigned)hbits(l0) | ((unsigned)hbits(l1) << 16);
}

// 4-product split GEMM (hi*hi + hi*lo + lo*hi + lo*lo)
__device__ __forceinline__ void mma4(float* d, const uint32_t* ah, const uint32_t* al,
                                     const uint32_t* bh, const uint32_t* bl) {
    MMA_F16(d[0], d[1], d[2], d[3], ah[0], ah[1], ah[2], ah[3], bh[0], bh[1]);
    MMA_F16(d[0], d[1], d[2], d[3], ah[0], ah[1], ah[2], ah[3], bl[0], bl[1]);
    MMA_F16(d[0], d[1], d[2], d[3], al[0], al[1], al[2], al[3], bh[0], bh[1]);
    MMA_F16(d[0], d[1], d[2], d[3], al[0], al[1], al[2], al[3], bl[0], bl[1]);
}

// ---------------------------------------------------------------------------
// Grid barrier among the NB prep CTAs (all co-resident)
// ---------------------------------------------------------------------------
__device__ __forceinline__ void grid_barrier() {
    __syncthreads();
    if (threadIdx.x == 0) {
        __threadfence();
        unsigned t = atomicAdd(&g_bar, 1u);
        unsigned target = (t / NB + 1u) * NB;
        volatile unsigned* p = &g_bar;
        while (*p < target) { }
        __threadfence();
    }
    __syncthreads();
}

// ---------------------------------------------------------------------------
// Build a K-major fp16-split smem image from f32 rows (prep NS passes).
// ---------------------------------------------------------------------------
__device__ __forceinline__ void build_img(char* dst, const float* __restrict__ src,
                                          int ld, int nrows, int diag_row0) {
    const int cstride = nrows * 128;
    const int sstride = cstride * 4;
    for (int tt = threadIdx.x; tt < nrows * 32; tt += 256) {
        const int row = tt >> 5, c0 = (tt & 31) * 8;
        float f[8];
        *(float4*)&f[0] = *(const float4*)&src[row * ld + c0];
        *(float4*)&f[4] = *(const float4*)&src[row * ld + c0 + 4];
        if (diag_row0 != NODIAG) {
            const int gr = diag_row0 + row;
#pragma unroll
            for (int j = 0; j < 8; ++j)
                f[j] = ((gr == c0 + j) ? 2.0f : 0.0f) - f[j];
        }
        unsigned uh[4], ul[4];
#pragma unroll
        for (int q = 0; q < 4; ++q)
            split2(f[2 * q], f[2 * q + 1], uh[q], ul[q]);
        const int chunk = c0 >> 6, g = (c0 & 63) >> 3;
        const int off = chunk * cstride + row * 128 + ((g ^ (row & 7)) << 4);
        *(uint4*)(dst + off) = make_uint4(uh[0], uh[1], uh[2], uh[3]);
        *(uint4*)(dst + sstride + off) = make_uint4(ul[0], ul[1], ul[2], ul[3]);
    }
}

// ---------------------------------------------------------------------------
// Prep kernel: NS chain ONLY (converter CTAs removed). 64 CTAs x 256 threads.
// ---------------------------------------------------------------------------
#define SMEM_PREP 98304

__global__ __launch_bounds__(256, 1)
void prep_kernel(const float* __restrict__ dict) {
    extern __shared__ __align__(1024) char pool[];
    const uint32_t pb = smem_u32(pool);
    const int bid = blockIdx.x;
    const int t = threadIdx.x;

    const int wid = t >> 5, lane = t & 31;
    const int i0 = (bid >> 3) * 32;
    const int j0 = (bid & 7) * 32;
    const int m0 = (wid & 1) * 16;
    const int n0 = (wid >> 1) * 8;
    const int er = lane >> 2, ec = (lane & 3) * 2;
    const int ar = m0 + (lane & 15), ag = lane >> 4;
    const int br = n0 + (lane & 7), bg = (lane >> 3) & 1;

    // ---------------- Phase 1: scalar gram G = dict^T dict, Y0 = aI + bG ---
    {
        float (*As)[34] = (float(*)[34])pool;
        float (*Bs)[34] = (float(*)[34])(pool + 32 * 34 * 4);
        const int tx = t & 15, ty = t >> 4;
        const int lr = t >> 3, lc = (t & 7) * 4;
        float a00 = 0.f, a01 = 0.f, a10 = 0.f, a11 = 0.f;
        for (int kc = 0; kc < KAT; kc += 32) {
            float4 va = *(const float4*)&dict[(kc + lr) * DIMD + i0 + lc];
            float4 vb = *(const float4*)&dict[(kc + lr) * DIMD + j0 + lc];
            As[lr][lc + 0] = va.x; As[lr][lc + 1] = va.y;
            As[lr][lc + 2] = va.z; As[lr][lc + 3] = va.w;
            Bs[lr][lc + 0] = vb.x; Bs[lr][lc + 1] = vb.y;
            Bs[lr][lc + 2] = vb.z; Bs[lr][lc + 3] = vb.w;
            __syncthreads();
#pragma unroll
            for (int k = 0; k < 32; ++k) {
                float2 a = *(const float2*)&As[k][ty * 2];
                float2 b = *(const float2*)&Bs[k][tx * 2];
                a00 += a.x * b.x; a01 += a.x * b.y;
                a10 += a.y * b.x; a11 += a.y * b.y;
            }
            __syncthreads();
        }
        const int r0 = i0 + ty * 2, c0 = j0 + tx * 2;
        float acc[2][2] = {{a00, a01}, {a10, a11}};
#pragma unroll
        for (int ii = 0; ii < 2; ++ii)
#pragma unroll
            for (int jj = 0; jj < 2; ++jj) {
                float g = acc[ii][jj];
                g_G[(r0 + ii) * DIMD + c0 + jj] = g;
                float y0 = B_COEF * g;
                if (r0 + ii == c0 + jj) y0 += A_COEF;
                g_Y[(r0 + ii) * DIMD + c0 + jj] = y0;
            }
    }
    grid_barrier();

    // ---------------- Init pass: Z0 = a*G + b*(G*G)  (G symmetric) ---------
    {
        build_img(pool,         g_G + i0 * DIMD, DIMD, 32, NODIAG);
        build_img(pool + 65536, g_G + j0 * DIMD, DIMD, 32, NODIAG);
        __syncthreads();
        float ac[4] = {0.f, 0.f, 0.f, 0.f};
#pragma unroll
        for (int c = 0; c < 4; ++c) {
            const uint32_t Ab = pb + c * 4096, Bb = pb + 65536 + c * 4096;
#pragma unroll
            for (int ks = 0; ks < 4; ++ks) {
                uint32_t ah[4], al[4], bh[2], bl[2];
                uint32_t aad = Ab + ar * 128 + (((ks * 2 + ag) ^ (ar & 7)) << 4);
                LDSM_X4(ah[0], ah[1], ah[2], ah[3], aad);
                LDSM_X4(al[0], al[1], al[2], al[3], aad + 16384);
                uint32_t bad = Bb + br * 128 + (((ks * 2 + bg) ^ (br & 7)) << 4);
                LDSM_X2(bh[0], bh[1], bad);
                LDSM_X2(bl[0], bl[1], bad + 16384);
                mma4(ac, ah, al, bh, bl);
            }
        }
        const int r0 = i0 + m0 + er, c0 = j0 + n0 + ec;
        g_Z[r0 * DIMD + c0]           = A_COEF * g_G[r0 * DIMD + c0]           + B_COEF * ac[0];
        g_Z[r0 * DIMD + c0 + 1]       = A_COEF * g_G[r0 * DIMD + c0 + 1]       + B_COEF * ac[1];
        g_Z[(r0 + 8) * DIMD + c0]     = A_COEF * g_G[(r0 + 8) * DIMD + c0]     + B_COEF * ac[2];
        g_Z[(r0 + 8) * DIMD + c0 + 1] = A_COEF * g_G[(r0 + 8) * DIMD + c0 + 1] + B_COEF * ac[3];
    }
    grid_barrier();

    // ---------------- Dual NS passes: Y' = Y*M, Z' = Z*M,  M = 2I - Z ------
    int p = 0;
    for (int it = 0; it < NDUAL; ++it) {
        const float* Yp = g_Y + p * DIMD * DIMD;
        const float* Zp = g_Z + p * DIMD * DIMD;
        build_img(pool,         Yp + i0 * DIMD, DIMD, 32, NODIAG);
        build_img(pool + 32768, Zp + i0 * DIMD, DIMD, 32, NODIAG);
        build_img(pool + 65536, Zp + j0 * DIMD, DIMD, 32, j0);
        __syncthreads();
        float aY[4] = {0.f, 0.f, 0.f, 0.f};
        float aZ[4] = {0.f, 0.f, 0.f, 0.f};
#pragma unroll
        for (int c = 0; c < 4; ++c) {
            const uint32_t A1 = pb + c * 4096;
            const uint32_t A2 = pb + 32768 + c * 4096;
            const uint32_t Bb = pb + 65536 + c * 4096;
#pragma unroll
            for (int ks = 0; ks < 4; ++ks) {
                uint32_t ah[4], al[4], zh[4], zl[4], bh[2], bl[2];
                const uint32_t aoff = ar * 128 + (((ks * 2 + ag) ^ (ar & 7)) << 4);
                LDSM_X4(ah[0], ah[1], ah[2], ah[3], A1 + aoff);
                LDSM_X4(al[0], al[1], al[2], al[3], A1 + aoff + 16384);
                LDSM_X4(zh[0], zh[1], zh[2], zh[3], A2 + aoff);
                LDSM_X4(zl[0], zl[1], zl[2], zl[3], A2 + aoff + 16384);
                uint32_t bad = Bb + br * 128 + (((ks * 2 + bg) ^ (br & 7)) << 4);
                LDSM_X2(bh[0], bh[1], bad);
                LDSM_X2(bl[0], bl[1], bad + 16384);
                mma4(aY, ah, al, bh, bl);
                mma4(aZ, zh, zl, bh, bl);
            }
        }
        float* Yn = g_Y + (p ^ 1) * DIMD * DIMD;
        float* Zn = g_Z + (p ^ 1) * DIMD * DIMD;
        const int r0 = i0 + m0 + er, c0 = j0 + n0 + ec;
        Yn[r0 * DIMD + c0] = aY[0];           Yn[r0 * DIMD + c0 + 1] = aY[1];
        Yn[(r0 + 8) * DIMD + c0] = aY[2];     Yn[(r0 + 8) * DIMD + c0 + 1] = aY[3];
        Zn[r0 * DIMD + c0] = aZ[0];           Zn[r0 * DIMD + c0 + 1] = aZ[1];
        Zn[(r0 + 8) * DIMD + c0] = aZ[2];     Zn[(r0 + 8) * DIMD + c0 + 1] = aZ[3];
        grid_barrier();
        p ^= 1;
    }

    // ---------------- Final pass: Yf = Y*(2I - Z) --------------------------
    {
        const float* Yp = g_Y + p * DIMD * DIMD;
        const float* Zp = g_Z + p * DIMD * DIMD;
        build_img(pool,         Yp + i0 * DIMD, DIMD, 32, NODIAG);
        build_img(pool + 65536, Zp + j0 * DIMD, DIMD, 32, j0);
        __syncthreads();
        float ac[4] = {0.f, 0.f, 0.f, 0.f};
#pragma unroll
        for (int c = 0; c < 4; ++c) {
            const uint32_t Ab = pb + c * 4096, Bb = pb + 65536 + c * 4096;
#pragma unroll
            for (int ks = 0; ks < 4; ++ks) {
                uint32_t ah[4], al[4], bh[2], bl[2];
                uint32_t aad = Ab + ar * 128 + (((ks * 2 + ag) ^ (ar & 7)) << 4);
                LDSM_X4(ah[0], ah[1], ah[2], ah[3], aad);
                LDSM_X4(al[0], al[1], al[2], al[3], aad + 16384);
                uint32_t bad = Bb + br * 128 + (((ks * 2 + bg) ^ (br & 7)) << 4);
                LDSM_X2(bh[0], bh[1], bad);
                LDSM_X2(bl[0], bl[1], bad + 16384);
                mma4(ac, ah, al, bh, bl);
            }
        }
        float* Yn = g_Y + (p ^ 1) * DIMD * DIMD;
        const int r0 = i0 + m0 + er, c0 = j0 + n0 + ec;
        Yn[r0 * DIMD + c0] = ac[0];           Yn[r0 * DIMD + c0 + 1] = ac[1];
        Yn[(r0 + 8) * DIMD + c0] = ac[2];     Yn[(r0 + 8) * DIMD + c0 + 1] = ac[3];
    }
    grid_barrier();
    p ^= 1;

    // ---------------- W pass -> g_Bimg (split+swizzled) --------------------
    {
        const float* Yf = g_Y + p * DIMD * DIMD;
        const int kt = bid >> 2, dbase = (bid & 3) * 64;
        build_img(pool,         dict + (size_t)kt * 32 * DIMD, DIMD, 32, NODIAG);
        build_img(pool + 32768, Yf + dbase * DIMD, DIMD, 64, NODIAG);
        __syncthreads();
        const int nb0 = (wid >> 1) * 16;
        float aw[2][4] = {{0.f, 0.f, 0.f, 0.f}, {0.f, 0.f, 0.f, 0.f}};
#pragma unroll
        for (int c = 0; c < 4; ++c) {
            const uint32_t Ab = pb + c * 4096;
            const uint32_t Bb = pb + 32768 + c * 8192;
#pragma unroll
            for (int ks = 0; ks < 4; ++ks) {
                uint32_t ah[4], al[4];
                uint32_t aad = Ab + ar * 128 + (((ks * 2 + ag) ^ (ar & 7)) << 4);
                LDSM_X4(ah[0], ah[1], ah[2], ah[3], aad);
                LDSM_X4(al[0], al[1], al[2], al[3], aad + 16384);
#pragma unroll
                for (int nf = 0; nf < 2; ++nf) {
                    const int brw = nb0 + nf * 8 + (lane & 7);
                    uint32_t bh[2], bl[2];
                    uint32_t bad = Bb + brw * 128 + (((ks * 2 + bg) ^ (brw & 7)) << 4);
                    LDSM_X2(bh[0], bh[1], bad);
                    LDSM_X2(bl[0], bl[1], bad + 32768);
                    mma4(aw[nf], ah, al, bh, bl);
                }
            }
        }
#pragma unroll
        for (int nf = 0; nf < 2; ++nf) {
#pragma unroll
            for (int h = 0; h < 2; ++h) {
                float v0 = aw[nf][h * 2 + 0], v1 = aw[nf][h * 2 + 1];
                const int m = m0 + er + h * 8;
                const int kat = kt * 32 + m;
                const int n = nb0 + nf * 8 + ec;
                const int kh = kat >> 8;
                const size_t imgbyte = (size_t)(kh * 4 + (bid & 3)) * 65536;
                const int row = kat & 255;
                const int off = row * 128 + (((n >> 3) ^ (row & 7)) << 4) + (n & 7) * 2;
                unsigned uh, ul;
                split2(v0, v1, uh, ul);
                *(uint32_t*)((char*)g_Bimg + imgbyte + off) = uh;
                *(uint32_t*)((char*)g_Bimg + imgbyte + 32768 + off) = ul;
            }
        }
    }
}

// ---------------------------------------------------------------------------
// In-kernel A convert: X f32 [d][n] -> k-major fp16-split image [64 d][128 n]
// rows = d (256 B hi), XOR-(row&7) swizzle on 16B groups; lo at +16384.
// Fully coalesced LDG (16 threads cover one 512B X row).
// ---------------------------------------------------------------------------
__device__ __forceinline__ void convert_a(uint32_t img, const float* __restrict__ X,
                                          int nt, int c) {
    const int n0 = nt * 128, d0 = c * 64;
    const int t = threadIdx.x;
#pragma unroll
    for (int q = 0; q < 4; ++q) {
        const int slot = t + 256 * q;
        const int row = slot >> 4, g = slot & 15;
        const float* src = X + (size_t)(d0 + row) * NCOL + n0 + g * 8;
        float4 v0 = *(const float4*)src;
        float4 v1 = *(const float4*)(src + 4);
        unsigned uh[4], ul[4];
        split2(v0.x, v0.y, uh[0], ul[0]);
        split2(v0.z, v0.w, uh[1], ul[1]);
        split2(v1.x, v1.y, uh[2], ul[2]);
        split2(v1.z, v1.w, uh[3], ul[3]);
        const uint32_t off = img + row * 256 + ((g ^ (row & 7)) << 4);
        STS128(off,         uh[0], uh[1], uh[2], uh[3]);
        STS128(off + 16384, ul[0], ul[1], ul[2], ul[3]);
    }
}

// ---------------------------------------------------------------------------
// Persistent tensor-core GEMM: out[n][k] = sum_d X[d][n] W[d][k]
// 148 CTAs x 256 threads (8 warps), CTA tile 128n x 256k, warp tile 64n x 64k.
// A converted IN-KERNEL from X (no g_Aimg): k-major image + ldmatrix.x4.trans.
// B via 2-stage cp.async.bulk from g_Bimg (unchanged from R15).
// smem: ctrl 1K + A img 2x32K + B 2x64K = 197632 B.
// ---------------------------------------------------------------------------
#define SMEM_MMA (1024 + 2 * 32768 + 2 * 65536)

__global__ __launch_bounds__(256, 1)
void out_mma_kernel(const float* __restrict__ X, float* __restrict__ out) {
    extern __shared__ __align__(1024) char smem[];
    const uint32_t sb = smem_u32(smem);
    const uint32_t BUFA = sb + 1024;              // 2 x 32768 (hi, lo at +16384)
    const uint32_t BUFB = sb + 1024 + 65536;      // 2 x 65536 (hi, lo at +32768)

    const int bid = blockIdx.x;
    const int t = threadIdx.x, wid = t >> 5, lane = t & 31;
    const int wn = wid & 1;          // n-half of CTA tile (64 rows)
    const int wkq = wid >> 1;        // k-quarter (64 cols)

    if (t == 0) {
        MBARRIER_INIT(sb + 0, 1);  MBARRIER_INIT(sb + 16, 1);   // B full[2]
        MBARRIER_INIT(sb + 32, 8); MBARRIER_INIT(sb + 48, 8);   // B empty[2]
    }
    __syncthreads();

    const int nitems = (1023 - bid) / 148 + 1;
    const int nc = nitems * 4;

    auto fill = [&](int cc) {
        const int item = bid + (cc >> 2) * 148;
        const int c = cc & 3;
        const int kh = item & 1;
        const uint32_t buf = BUFB + (uint32_t)(cc & 1) * 65536;
        const uint32_t mb = sb + (uint32_t)(cc & 1) * 16;
        MBARRIER_EXPECT_TX(mb, 65536u);
        bulk_g2s(buf, (const char*)g_Bimg + (size_t)(kh * 4 + c) * 65536, 65536u, mb);
    };
    if (t == 0) { fill(0); if (nc > 1) fill(1); }

    // A trans-fragment addressing: octet layout
    //   lanes 0-7: k 0-7, m+0 | 8-15: k 0-7, m+8 | 16-23: k 8-15, m+0 | 24-31: k 8-15, m+8
    const int l8 = lane & 7, oct = lane >> 3;
    const int a_krow = ((oct >> 1) << 3) + l8;    // k-offset within 16
    const int a_mg = oct & 1;                      // +1 group = +8 n
    // B addressing (unchanged from R15)
    const int b_rowoff = ((lane >> 4) << 3) + (lane & 7);
    const int b_gsel = (lane >> 3) & 1;

    float acc[4][8][4];

    // prologue: convert chunk 0's A image
    convert_a(BUFA, X, bid >> 1, 0);
    __syncthreads();

    for (int cc = 0; cc < nc; ++cc) {
        const int c = cc & 3;
        if (c == 0) {
#pragma unroll
            for (int mf = 0; mf < 4; ++mf)
#pragma unroll
                for (int nf = 0; nf < 8; ++nf)
#pragma unroll
                    for (int q = 0; q < 4; ++q) acc[mf][nf][q] = 0.f;
        }
        const uint32_t st = (uint32_t)(cc & 1);
        const uint32_t par = (uint32_t)((cc >> 1) & 1);
        MBARRIER_WAIT_PARITY(sb + st * 16, par);

        // convert next chunk's A (independent buffer; interleaves with MMA)
        if (cc + 1 < nc) {
            const int item2 = bid + ((cc + 1) >> 2) * 148;
            convert_a(BUFA + (uint32_t)((cc + 1) & 1) * 32768, X,
                      item2 >> 1, (cc + 1) & 3);
        }

        const uint32_t Ahi = BUFA + st * 32768, Alo = Ahi + 16384;
        const uint32_t Bhi = BUFB + st * 65536, Blo = Bhi + 32768;

#pragma unroll
        for (int ks = 0; ks < 4; ++ks) {
            const int g = ks * 2;
            uint32_t ah[4][4], al[4][4];
#pragma unroll
            for (int mf = 0; mf < 4; ++mf) {
                const int row = ks * 16 + a_krow;                       // d-local
                const int ng = wn * 8 + mf * 2 + a_mg;                  // n-group
                const uint32_t aoff = row * 256 + ((ng ^ (row & 7)) << 4);
                LDSM_X4T(ah[mf][0], ah[mf][1], ah[mf][2], ah[mf][3], Ahi + aoff);
                LDSM_X4T(al[mf][0], al[mf][1], al[mf][2], al[mf][3], Alo + aoff);
            }
#pragma unroll
            for (int nfp = 0; nfp < 4; ++nfp) {
                const int row = wkq * 64 + nfp * 16 + b_rowoff;
                const uint32_t boff = row * 128 + (((g + b_gsel) ^ (row & 7)) << 4);
                uint32_t bh[4], bl[4];
                LDSM_X4(bh[0], bh[1], bh[2], bh[3], Bhi + boff);
                LDSM_X4(bl[0], bl[1], bl[2], bl[3], Blo + boff);
#pragma unroll
                for (int j = 0; j < 2; ++j) {
                    const int nf = nfp * 2 + j;
#pragma unroll
                    for (int mf = 0; mf < 4; ++mf) {
                        float* d = acc[mf][nf];
                        MMA_F16(d[0], d[1], d[2], d[3],
                                ah[mf][0], ah[mf][1], ah[mf][2], ah[mf][3],
                                bh[j * 2], bh[j * 2 + 1]);
                        MMA_F16(d[0], d[1], d[2], d[3],
                                ah[mf][0], ah[mf][1], ah[mf][2], ah[mf][3],
                                bl[j * 2], bl[j * 2 + 1]);
                        MMA_F16(d[0], d[1], d[2], d[3],
                                al[mf][0], al[mf][1], al[mf][2], al[mf][3],
                                bh[j * 2], bh[j * 2 + 1]);
                    }
                }
            }
        }

        // release B stage; producer refills
        if (lane == 0) MBARRIER_ARRIVE(sb + 32 + st * 16);
        if (t == 0 && cc + 2 < nc) {
            MBARRIER_WAIT_PARITY(sb + 32 + st * 16, par);
            fill(cc + 2);
        }

        if (c == 3) {                    // epilogue for this item
            const int item = bid + (cc >> 2) * 148;
            const int nt = item >> 1, kh = item & 1;
            const int er = lane >> 2, ec = (lane & 3) * 2;
            const size_t nbase = (size_t)nt * 128 + wn * 64 + er;
            const int kbase = kh * 256 + wkq * 64 + ec;
#pragma unroll
            for (int mf = 0; mf < 4; ++mf) {
                const size_t r0 = nbase + mf * 16;
#pragma unroll
                for (int nf = 0; nf < 8; ++nf) {
                    const int col = kbase + nf * 8;
                    float* d = acc[mf][nf];
                    *(float2*)&out[r0 * KAT + col]       = make_float2(d[0], d[1]);
                    *(float2*)&out[(r0 + 8) * KAT + col] = make_float2(d[2], d[3]);
                }
            }
        }
        __syncthreads();   // A image for cc+1 fully written before next iter's ldmatrix
    }
}

// ---------------------------------------------------------------------------
// Launch: 2 graph nodes, no allocations, deterministic, replay-safe.
// ---------------------------------------------------------------------------
extern "C" void kernel_launch(void* const* d_in, const int* in_sizes, int n_in,
                              void* d_out, int out_size) {
    (void)in_sizes; (void)n_in; (void)out_size;
    const float* z_e  = (const float*)d_in[0];   // [DIMD, NCOL]
    const float* dict = (const float*)d_in[1];   // [KAT, DIMD]
    float* out = (float*)d_out;                  // [NCOL, KAT]

    cudaFuncSetAttribute(prep_kernel,
                         cudaFuncAttributeMaxDynamicSharedMemorySize, SMEM_PREP);
    cudaFuncSetAttribute(out_mma_kernel,
                         cudaFuncAttributeMaxDynamicSharedMemorySize, SMEM_MMA);

    // 1) NS-only prep (64 CTAs): gram + Chebyshev + 6 dual NS + final + W imgs
    prep_kernel<<<NB, 256, SMEM_PREP>>>(dict);

    // 2) persistent tensor-core GEMM with in-kernel X->fp16-split conversion
    //    (g_Aimg round-trip eliminated: saves ~128 MB of DRAM traffic)
    out_mma_kernel<<<148, 256, SMEM_MMA>>>(z_e, out);
}

// round 17
// speedup vs baseline: 1.2657x; 1.2657x over previous
#include <cuda_runtime.h>
#include <cuda_fp16.h>
#include <cstdint>

// Problem constants
#define DIMD 256
#define KAT  512
#define NCOL 65536
#define NB   64          // prep CTAs (barrier group)
#define NCONV 84         // converter CTAs (NB+NCONV = 148 SMs, all co-resident)
#define NDUAL 5          // dual Newton-Schulz passes (then one final Y-only pass)
                         // residual 0.865^64 ~ 9.3e-5, below the ~3.5e-4 drift floor

// Chebyshev degree-1 start for Newton-Schulz (residual 0.865 on [30,1600])
#define A_COEF 4.57720e-3f
#define B_COEF (-2.80809e-6f)
#define NODIAG (-1000000)

// ---------------------------------------------------------------------------
// Device scratch (no allocations allowed)
// ---------------------------------------------------------------------------
__device__ float g_G[DIMD * DIMD];
__device__ float g_Y[2 * DIMD * DIMD];    // Y ping-pong
__device__ float g_Z[2 * DIMD * DIMD];    // Z = G*Y ping-pong
__device__ unsigned g_bar = 0;            // monotone grid barrier

// Pre-swizzled fp16-split images (XOR swizzle within 128B rows):
// A: per (ntile 0..511, dchunk 0..3): [split 2][128 n][64 d] = 32768 B each
__device__ __align__(1024) __half g_Aimg[512 * 4 * 2 * 8192];   // 64 MB
// B: per (img = kh*4+chunk, 8 imgs): [split 2][256 k][64 d] = 65536 B each
__device__ __align__(1024) __half g_Bimg[8 * 2 * 16384];        // 512 KB

// ---------------------------------------------------------------------------
// PTX helpers (portable PTX only — no 'a'-suffix features)
// ---------------------------------------------------------------------------
__device__ __forceinline__ uint32_t smem_u32(const void* p) {
    uint32_t a;
    asm("{ .reg .u64 tmp; cvta.to.shared.u64 tmp, %1; cvt.u32.u64 %0, tmp; }"
        : "=r"(a) : "l"(p));
    return a;
}

#define MBARRIER_INIT(addr, cnt) \
    asm volatile("mbarrier.init.shared.b64 [%0], %1;" :: "r"(addr), "r"(cnt) : "memory")
#define MBARRIER_EXPECT_TX(addr, bytes) \
    asm volatile("mbarrier.arrive.expect_tx.shared.b64 _, [%0], %1;" \
                 :: "r"(addr), "r"(bytes) : "memory")
#define MBARRIER_ARRIVE(addr) \
    asm volatile("mbarrier.arrive.shared.b64 _, [%0];" :: "r"(addr) : "memory")

#define MBARRIER_WAIT_PARITY(addr, par) do {                                   \
    uint32_t _m = (addr), _p = (par), _done;                                   \
    asm volatile("{\n\t.reg .pred p;\n\t"                                      \
        "mbarrier.try_wait.parity.acquire.cta.shared::cta.b64 p, [%1], %2;\n\t"\
        "selp.b32 %0, 1, 0, p;\n\t}"                                           \
        : "=r"(_done) : "r"(_m), "r"(_p) : "memory");                          \
    if (!_done) {                                                              \
        asm volatile("{\n\t.reg .pred P1;\n\t"                                 \
            "WL_%=:\n\t"                                                       \
            "mbarrier.try_wait.parity.acquire.cta.shared::cta.b64 P1, [%0], %1, 0x989680;\n\t" \
            "@P1 bra.uni WD_%=;\n\t"                                           \
            "bra.uni WL_%=;\n\t"                                               \
            "WD_%=:\n\t}"                                                      \
            :: "r"(_m), "r"(_p) : "memory");                                   \
    }                                                                          \
} while (0)

__device__ __forceinline__ void bulk_g2s(uint32_t dst, const void* src,
                                         uint32_t bytes, uint32_t mbar) {
    asm volatile("cp.async.bulk.shared::cta.global.mbarrier::complete_tx::bytes "
                 "[%0], [%1], %2, [%3];"
                 :: "r"(dst), "l"(src), "r"(bytes), "r"(mbar) : "memory");
}

#define LDSM_X4(r0, r1, r2, r3, a) \
    asm volatile("ldmatrix.sync.aligned.m8n8.x4.shared.b16 {%0,%1,%2,%3}, [%4];" \
        : "=r"(r0), "=r"(r1), "=r"(r2), "=r"(r3) : "r"(a))
#define LDSM_X2(r0, r1, a) \
    asm volatile("ldmatrix.sync.aligned.m8n8.x2.shared.b16 {%0,%1}, [%2];" \
        : "=r"(r0), "=r"(r1) : "r"(a))

#define MMA_F16(d0, d1, d2, d3, a0, a1, a2, a3, b0, b1) \
    asm volatile("mma.sync.aligned.m16n8k16.row.col.f32.f16.f16.f32 " \
        "{%0,%1,%2,%3}, {%4,%5,%6,%7}, {%8,%9}, {%0,%1,%2,%3};" \
        : "+f"(d0), "+f"(d1), "+f"(d2), "+f"(d3) \
        : "r"(a0), "r"(a1), "r"(a2), "r"(a3), "r"(b0), "r"(b1))

__device__ __forceinline__ unsigned short hbits(__half h) {
    return *reinterpret_cast<unsigned short*>(&h);
}

// pack two floats into one fp16x2 hi word + one fp16x2 lo word
__device__ __forceinline__ void split2(float v0, float v1, unsigned& uh, unsigned& ul) {
    __half h0 = __float2half_rn(v0);
    __half h1 = __float2half_rn(v1);
    __half l0 = __float2half_rn(v0 - __half2float(h0));
    __half l1 = __float2half_rn(v1 - __half2float(h1));
    uh = (unsigned)hbits(h0) | ((unsigned)hbits(h1) << 16);
    ul = (unsigned)hbits(l0) | ((unsigned)hbits(l1) << 16);
}

// 4-product split GEMM (hi*hi + hi*lo + lo*hi + lo*lo)
__device__ __forceinline__ void mma4(float* d, const uint32_t* ah, const uint32_t* al,
                                     const uint32_t* bh, const uint32_t* bl) {
    MMA_F16(d[0], d[1], d[2], d[3], ah[0], ah[1], ah[2], ah[3], bh[0], bh[1]);
    MMA_F16(d[0], d[1], d[2], d[3], ah[0], ah[1], ah[2], ah[3], bl[0], bl[1]);
    MMA_F16(d[0], d[1], d[2], d[3], al[0], al[1], al[2], al[3], bh[0], bh[1]);
    MMA_F16(d[0], d[1], d[2], d[3], al[0], al[1], al[2], al[3], bl[0], bl[1]);
}

// ---------------------------------------------------------------------------
// Grid barrier among the NB prep CTAs (all co-resident)
// ---------------------------------------------------------------------------
__device__ __forceinline__ void grid_barrier() {
    __syncthreads();
    if (threadIdx.x == 0) {
        __threadfence();
        unsigned t = atomicAdd(&g_bar, 1u);
        unsigned target = (t / NB + 1u) * NB;
        volatile unsigned* p = &g_bar;
        while (*p < target) { }
        __threadfence();
    }
    __syncthreads();
}

// ---------------------------------------------------------------------------
// Build a K-major fp16-split smem image from f32 rows.
// ---------------------------------------------------------------------------
__device__ __forceinline__ void build_img(char* dst, const float* __restrict__ src,
                                          int ld, int nrows, int diag_row0) {
    const int cstride = nrows * 128;
    const int sstride = cstride * 4;
    for (int tt = threadIdx.x; tt < nrows * 32; tt += 256) {
        const int row = tt >> 5, c0 = (tt & 31) * 8;
        float f[8];
        *(float4*)&f[0] = *(const float4*)&src[row * ld + c0];
        *(float4*)&f[4] = *(const float4*)&src[row * ld + c0 + 4];
        if (diag_row0 != NODIAG) {
            const int gr = diag_row0 + row;
#pragma unroll
            for (int j = 0; j < 8; ++j)
                f[j] = ((gr == c0 + j) ? 2.0f : 0.0f) - f[j];
        }
        unsigned uh[4], ul[4];
#pragma unroll
        for (int q = 0; q < 4; ++q)
            split2(f[2 * q], f[2 * q + 1], uh[q], ul[q]);
        const int chunk = c0 >> 6, g = (c0 & 63) >> 3;
        const int off = chunk * cstride + row * 128 + ((g ^ (row & 7)) << 4);
        *(uint4*)(dst + off) = make_uint4(uh[0], uh[1], uh[2], uh[3]);
        *(uint4*)(dst + sstride + off) = make_uint4(ul[0], ul[1], ul[2], ul[3]);
    }
}

// ---------------------------------------------------------------------------
// Prep kernel, 148 CTAs x 256 threads, 98304 B dynamic smem:
//   bid <  64 : scalar gram (+Y0) -> HMMA init/dual/final NS passes -> W imgs
//   bid >= 64 : convert X -> fp16-split swizzled A images (concurrent)
// ---------------------------------------------------------------------------
#define SMEM_PREP 98304

__global__ __launch_bounds__(256, 1)
void prep_kernel(const float* __restrict__ dict, const float* __restrict__ X) {
    extern __shared__ __align__(1024) char pool[];
    const uint32_t pb = smem_u32(pool);
    const int bid = blockIdx.x;
    const int t = threadIdx.x;

    // =========================== Converter CTAs ============================
    if (bid >= NB) {
        float (*Sx)[132] = (float(*)[132])pool;
        for (int tile = bid - NB; tile < 2048; tile += NCONV) {
            const int nt = tile >> 2, c = tile & 3;
            const int nn0 = nt * 128, d0 = c * 64;
            {
                const int dl = t >> 5, n4 = (t & 31) * 4;
#pragma unroll
                for (int j = 0; j < 8; ++j) {
                    float4 v = *(const float4*)&X[(size_t)(d0 + dl + j * 8) * NCOL + nn0 + n4];
                    *(float4*)&Sx[dl + j * 8][n4] = v;
                }
            }
            __syncthreads();
            {
                const int m = t >> 1, half = t & 1;
                char* pA = (char*)g_Aimg + (size_t)tile * 32768;
#pragma unroll
                for (int gl = 0; gl < 4; ++gl) {
                    unsigned uh[4], ul[4];
#pragma unroll
                    for (int q = 0; q < 4; ++q) {
                        int i0 = gl * 8 + q * 2;
                        split2(Sx[half * 32 + i0][m], Sx[half * 32 + i0 + 1][m],
                               uh[q], ul[q]);
                    }
                    int g = half * 4 + gl;
                    int off = m * 128 + ((g ^ (m & 7)) << 4);
                    *(uint4*)(pA + off)         = make_uint4(uh[0], uh[1], uh[2], uh[3]);
                    *(uint4*)(pA + 16384 + off) = make_uint4(ul[0], ul[1], ul[2], ul[3]);
                }
            }
            __syncthreads();
        }
        return;
    }

    // ============================= Prep CTAs ===============================
    const int wid = t >> 5, lane = t & 31;
    const int i0 = (bid >> 3) * 32;
    const int j0 = (bid & 7) * 32;
    const int m0 = (wid & 1) * 16;
    const int n0 = (wid >> 1) * 8;
    const int er = lane >> 2, ec = (lane & 3) * 2;
    const int ar = m0 + (lane & 15), ag = lane >> 4;
    const int br = n0 + (lane & 7), bg = (lane >> 3) & 1;

    // ---------------- Phase 1: scalar gram G = dict^T dict, Y0 = aI + bG ---
    {
        float (*As)[34] = (float(*)[34])pool;
        float (*Bs)[34] = (float(*)[34])(pool + 32 * 34 * 4);
        const int tx = t & 15, ty = t >> 4;
        const int lr = t >> 3, lc = (t & 7) * 4;
        float a00 = 0.f, a01 = 0.f, a10 = 0.f, a11 = 0.f;
        for (int kc = 0; kc < KAT; kc += 32) {
            float4 va = *(const float4*)&dict[(kc + lr) * DIMD + i0 + lc];
            float4 vb = *(const float4*)&dict[(kc + lr) * DIMD + j0 + lc];
            As[lr][lc + 0] = va.x; As[lr][lc + 1] = va.y;
            As[lr][lc + 2] = va.z; As[lr][lc + 3] = va.w;
            Bs[lr][lc + 0] = vb.x; Bs[lr][lc + 1] = vb.y;
            Bs[lr][lc + 2] = vb.z; Bs[lr][lc + 3] = vb.w;
            __syncthreads();
#pragma unroll
            for (int k = 0; k < 32; ++k) {
                float2 a = *(const float2*)&As[k][ty * 2];
                float2 b = *(const float2*)&Bs[k][tx * 2];
                a00 += a.x * b.x; a01 += a.x * b.y;
                a10 += a.y * b.x; a11 += a.y * b.y;
            }
            __syncthreads();
        }
        const int r0 = i0 + ty * 2, c0 = j0 + tx * 2;
        float acc[2][2] = {{a00, a01}, {a10, a11}};
#pragma unroll
        for (int ii = 0; ii < 2; ++ii)
#pragma unroll
            for (int jj = 0; jj < 2; ++jj) {
                float g = acc[ii][jj];
                g_G[(r0 + ii) * DIMD + c0 + jj] = g;
                float y0 = B_COEF * g;
                if (r0 + ii == c0 + jj) y0 += A_COEF;
                g_Y[(r0 + ii) * DIMD + c0 + jj] = y0;
            }
    }
    grid_barrier();

    // ---------------- Init pass: Z0 = a*G + b*(G*G)  (G symmetric) ---------
    {
        build_img(pool,         g_G + i0 * DIMD, DIMD, 32, NODIAG);
        build_img(pool + 65536, g_G + j0 * DIMD, DIMD, 32, NODIAG);
        __syncthreads();
        float ac[4] = {0.f, 0.f, 0.f, 0.f};
#pragma unroll
        for (int c = 0; c < 4; ++c) {
            const uint32_t Ab = pb + c * 4096, Bb = pb + 65536 + c * 4096;
#pragma unroll
            for (int ks = 0; ks < 4; ++ks) {
                uint32_t ah[4], al[4], bh[2], bl[2];
                uint32_t aad = Ab + ar * 128 + (((ks * 2 + ag) ^ (ar & 7)) << 4);
                LDSM_X4(ah[0], ah[1], ah[2], ah[3], aad);
                LDSM_X4(al[0], al[1], al[2], al[3], aad + 16384);
                uint32_t bad = Bb + br * 128 + (((ks * 2 + bg) ^ (br & 7)) << 4);
                LDSM_X2(bh[0], bh[1], bad);
                LDSM_X2(bl[0], bl[1], bad + 16384);
                mma4(ac, ah, al, bh, bl);
            }
        }
        const int r0 = i0 + m0 + er, c0 = j0 + n0 + ec;
        g_Z[r0 * DIMD + c0]           = A_COEF * g_G[r0 * DIMD + c0]           + B_COEF * ac[0];
        g_Z[r0 * DIMD + c0 + 1]       = A_COEF * g_G[r0 * DIMD + c0 + 1]       + B_COEF * ac[1];
        g_Z[(r0 + 8) * DIMD + c0]     = A_COEF * g_G[(r0 + 8) * DIMD + c0]     + B_COEF * ac[2];
        g_Z[(r0 + 8) * DIMD + c0 + 1] = A_COEF * g_G[(r0 + 8) * DIMD + c0 + 1] + B_COEF * ac[3];
    }
    grid_barrier();

    // ---------------- Dual NS passes: Y' = Y*M, Z' = Z*M,  M = 2I - Z ------
    int p = 0;
    for (int it = 0; it < NDUAL; ++it) {
        const float* Yp = g_Y + p * DIMD * DIMD;
        const float* Zp = g_Z + p * DIMD * DIMD;
        build_img(pool,         Yp + i0 * DIMD, DIMD, 32, NODIAG);
        build_img(pool + 32768, Zp + i0 * DIMD, DIMD, 32, NODIAG);
        build_img(pool + 65536, Zp + j0 * DIMD, DIMD, 32, j0);
        __syncthreads();
        float aY[4] = {0.f, 0.f, 0.f, 0.f};
        float aZ[4] = {0.f, 0.f, 0.f, 0.f};
#pragma unroll
        for (int c = 0; c < 4; ++c) {
            const uint32_t A1 = pb + c * 4096;
            const uint32_t A2 = pb + 32768 + c * 4096;
            const uint32_t Bb = pb + 65536 + c * 4096;
#pragma unroll
            for (int ks = 0; ks < 4; ++ks) {
                uint32_t ah[4], al[4], zh[4], zl[4], bh[2], bl[2];
                const uint32_t aoff = ar * 128 + (((ks * 2 + ag) ^ (ar & 7)) << 4);
                LDSM_X4(ah[0], ah[1], ah[2], ah[3], A1 + aoff);
                LDSM_X4(al[0], al[1], al[2], al[3], A1 + aoff + 16384);
                LDSM_X4(zh[0], zh[1], zh[2], zh[3], A2 + aoff);
                LDSM_X4(zl[0], zl[1], zl[2], zl[3], A2 + aoff + 16384);
                uint32_t bad = Bb + br * 128 + (((ks * 2 + bg) ^ (br & 7)) << 4);
                LDSM_X2(bh[0], bh[1], bad);
                LDSM_X2(bl[0], bl[1], bad + 16384);
                mma4(aY, ah, al, bh, bl);
                mma4(aZ, zh, zl, bh, bl);
            }
        }
        float* Yn = g_Y + (p ^ 1) * DIMD * DIMD;
        float* Zn = g_Z + (p ^ 1) * DIMD * DIMD;
        const int r0 = i0 + m0 + er, c0 = j0 + n0 + ec;
        Yn[r0 * DIMD + c0] = aY[0];           Yn[r0 * DIMD + c0 + 1] = aY[1];
        Yn[(r0 + 8) * DIMD + c0] = aY[2];     Yn[(r0 + 8) * DIMD + c0 + 1] = aY[3];
        Zn[r0 * DIMD + c0] = aZ[0];           Zn[r0 * DIMD + c0 + 1] = aZ[1];
        Zn[(r0 + 8) * DIMD + c0] = aZ[2];     Zn[(r0 + 8) * DIMD + c0 + 1] = aZ[3];
        grid_barrier();
        p ^= 1;
    }

    // ---------------- Final pass: Yf = Y*(2I - Z) --------------------------
    {
        const float* Yp = g_Y + p * DIMD * DIMD;
        const float* Zp = g_Z + p * DIMD * DIMD;
        build_img(pool,         Yp + i0 * DIMD, DIMD, 32, NODIAG);
        build_img(pool + 65536, Zp + j0 * DIMD, DIMD, 32, j0);
        __syncthreads();
        float ac[4] = {0.f, 0.f, 0.f, 0.f};
#pragma unroll
        for (int c = 0; c < 4; ++c) {
            const uint32_t Ab = pb + c * 4096, Bb = pb + 65536 + c * 4096;
#pragma unroll
            for (int ks = 0; ks < 4; ++ks) {
                uint32_t ah[4], al[4], bh[2], bl[2];
                uint32_t aad = Ab + ar * 128 + (((ks * 2 + ag) ^ (ar & 7)) << 4);
                LDSM_X4(ah[0], ah[1], ah[2], ah[3], aad);
                LDSM_X4(al[0], al[1], al[2], al[3], aad + 16384);
                uint32_t bad = Bb + br * 128 + (((ks * 2 + bg) ^ (br & 7)) << 4);
                LDSM_X2(bh[0], bh[1], bad);
                LDSM_X2(bl[0], bl[1], bad + 16384);
                mma4(ac, ah, al, bh, bl);
            }
        }
        float* Yn = g_Y + (p ^ 1) * DIMD * DIMD;
        const int r0 = i0 + m0 + er, c0 = j0 + n0 + ec;
        Yn[r0 * DIMD + c0] = ac[0];           Yn[r0 * DIMD + c0 + 1] = ac[1];
        Yn[(r0 + 8) * DIMD + c0] = ac[2];     Yn[(r0 + 8) * DIMD + c0 + 1] = ac[3];
    }
    grid_barrier();
    p ^= 1;

    // ---------------- W pass -> g_Bimg (split+swizzled) --------------------
    {
        const float* Yf = g_Y + p * DIMD * DIMD;
        const int kt = bid >> 2, dbase = (bid & 3) * 64;
        build_img(pool,         dict + (size_t)kt * 32 * DIMD, DIMD, 32, NODIAG);
        build_img(pool + 32768, Yf + dbase * DIMD, DIMD, 64, NODIAG);
        __syncthreads();
        const int nb0 = (wid >> 1) * 16;
        float aw[2][4] = {{0.f, 0.f, 0.f, 0.f}, {0.f, 0.f, 0.f, 0.f}};
#pragma unroll
        for (int c = 0; c < 4; ++c) {
            const uint32_t Ab = pb + c * 4096;
            const uint32_t Bb = pb + 32768 + c * 8192;
#pragma unroll
            for (int ks = 0; ks < 4; ++ks) {
                uint32_t ah[4], al[4];
                uint32_t aad = Ab + ar * 128 + (((ks * 2 + ag) ^ (ar & 7)) << 4);
                LDSM_X4(ah[0], ah[1], ah[2], ah[3], aad);
                LDSM_X4(al[0], al[1], al[2], al[3], aad + 16384);
#pragma unroll
                for (int nf = 0; nf < 2; ++nf) {
                    const int brw = nb0 + nf * 8 + (lane & 7);
                    uint32_t bh[2], bl[2];
                    uint32_t bad = Bb + brw * 128 + (((ks * 2 + bg) ^ (brw & 7)) << 4);
                    LDSM_X2(bh[0], bh[1], bad);
                    LDSM_X2(bl[0], bl[1], bad + 32768);
                    mma4(aw[nf], ah, al, bh, bl);
                }
            }
        }
#pragma unroll
        for (int nf = 0; nf < 2; ++nf) {
#pragma unroll
            for (int h = 0; h < 2; ++h) {
                float v0 = aw[nf][h * 2 + 0], v1 = aw[nf][h * 2 + 1];
                const int m = m0 + er + h * 8;
                const int kat = kt * 32 + m;
                const int n = nb0 + nf * 8 + ec;
                const int kh = kat >> 8;
                const size_t imgbyte = (size_t)(kh * 4 + (bid & 3)) * 65536;
                const int row = kat & 255;
                const int off = row * 128 + (((n >> 3) ^ (row & 7)) << 4) + (n & 7) * 2;
                unsigned uh, ul;
                split2(v0, v1, uh, ul);
                *(uint32_t*)((char*)g_Bimg + imgbyte + off) = uh;
                *(uint32_t*)((char*)g_Bimg + imgbyte + 32768 + off) = ul;
            }
        }
    }
}

// ---------------------------------------------------------------------------
// Persistent tensor-core GEMM: out[n][k] = sum_d X[d][n] W[d][k]
// 148 CTAs x 256 threads (8 warps). CTA tile 128n x 256k (one khalf),
// warp tile 64n x 64k (mf4 x nf8) -> A-frag reuse 8x, 85 B LDS per MMA.
// Items = 512 ntiles x 2 khalves = 1024 (~7/CTA). d in 4 chunks of 64.
// 2-stage pipeline; stage (98304 B): Ahi +0, Alo +16K, Bhi +32K, Blo +64K.
// B fragments loaded as ldmatrix X4 pairs (two nf blocks per instruction).
// ---------------------------------------------------------------------------
#define SMEM_MMA (1024 + 2 * 98304)

__global__ __launch_bounds__(256, 1)
void out_mma_kernel(float* __restrict__ out) {
    extern __shared__ __align__(1024) char smem[];
    const uint32_t sb = smem_u32(smem);
    const uint32_t BUF0 = sb + 1024;

    const int bid = blockIdx.x;
    const int t = threadIdx.x, wid = t >> 5, lane = t & 31;
    const int wn = wid & 1;          // n-half of CTA tile (64 rows)
    const int wkq = wid >> 1;        // k-quarter (64 cols)

    if (t == 0) {
        MBARRIER_INIT(sb + 0, 1);  MBARRIER_INIT(sb + 16, 1);   // full[2]
        MBARRIER_INIT(sb + 32, 8); MBARRIER_INIT(sb + 48, 8);   // empty[2]
    }
    __syncthreads();

    const int nitems = (1023 - bid) / 148 + 1;
    const int nc = nitems * 4;

    auto fill = [&](int cc) {
        const int item = bid + (cc >> 2) * 148;
        const int c = cc & 3;
        const int nt = item >> 1, kh = item & 1;
        const uint32_t buf = BUF0 + (uint32_t)(cc & 1) * 98304;
        const uint32_t mb = sb + (uint32_t)(cc & 1) * 16;
        MBARRIER_EXPECT_TX(mb, 98304u);
        bulk_g2s(buf, (const char*)g_Aimg + (size_t)nt * 131072 + (size_t)c * 32768,
                 32768u, mb);
        bulk_g2s(buf + 32768,
                 (const char*)g_Bimg + (size_t)(kh * 4 + c) * 65536, 65536u, mb);
    };
    if (t == 0) { fill(0); if (nc > 1) fill(1); }

    const int a_row = lane & 15, a_gsel = lane >> 4;
    const int b_rowoff = ((lane >> 4) << 3) + (lane & 7);
    const int b_gsel = (lane >> 3) & 1;

    float acc[4][8][4];

    for (int cc = 0; cc < nc; ++cc) {
        const int c = cc & 3;
        if (c == 0) {
#pragma unroll
            for (int mf = 0; mf < 4; ++mf)
#pragma unroll
                for (int nf = 0; nf < 8; ++nf)
#pragma unroll
                    for (int q = 0; q < 4; ++q) acc[mf][nf][q] = 0.f;
        }
        const uint32_t st = (uint32_t)(cc & 1);
        const uint32_t par = (uint32_t)((cc >> 1) & 1);
        MBARRIER_WAIT_PARITY(sb + st * 16, par);
        const uint32_t buf = BUF0 + st * 98304;
        const uint32_t Ahi = buf, Alo = buf + 16384;
        const uint32_t Bhi = buf + 32768, Blo = buf + 65536;

#pragma unroll
        for (int ks = 0; ks < 4; ++ks) {
            const int g = ks * 2;
            uint32_t ah[4][4], al[4][4];
#pragma unroll
            for (int mf = 0; mf < 4; ++mf) {
                const int row = wn * 64 + mf * 16 + a_row;
                const uint32_t aoff = row * 128 + (((g + a_gsel) ^ (row & 7)) << 4);
                LDSM_X4(ah[mf][0], ah[mf][1], ah[mf][2], ah[mf][3], Ahi + aoff);
                LDSM_X4(al[mf][0], al[mf][1], al[mf][2], al[mf][3], Alo + aoff);
            }
#pragma unroll
            for (int nfp = 0; nfp < 4; ++nfp) {
                const int row = wkq * 64 + nfp * 16 + b_rowoff;
                const uint32_t boff = row * 128 + (((g + b_gsel) ^ (row & 7)) << 4);
                uint32_t bh[4], bl[4];
                LDSM_X4(bh[0], bh[1], bh[2], bh[3], Bhi + boff);
                LDSM_X4(bl[0], bl[1], bl[2], bl[3], Blo + boff);
#pragma unroll
                for (int j = 0; j < 2; ++j) {
                    const int nf = nfp * 2 + j;
#pragma unroll
                    for (int mf = 0; mf < 4; ++mf) {
                        float* d = acc[mf][nf];
                        MMA_F16(d[0], d[1], d[2], d[3],
                                ah[mf][0], ah[mf][1], ah[mf][2], ah[mf][3],
                                bh[j * 2], bh[j * 2 + 1]);
                        MMA_F16(d[0], d[1], d[2], d[3],
                                ah[mf][0], ah[mf][1], ah[mf][2], ah[mf][3],
                                bl[j * 2], bl[j * 2 + 1]);
                        MMA_F16(d[0], d[1], d[2], d[3],
                                al[mf][0], al[mf][1], al[mf][2], al[mf][3],
                                bh[j * 2], bh[j * 2 + 1]);
                    }
                }
            }
        }

        // release this stage (per-warp arrival; no CTA-wide sync)
        if (lane == 0) MBARRIER_ARRIVE(sb + 32 + st * 16);
        // producer: wait for all 8 warps to release, then refill stage
        if (t == 0 && cc + 2 < nc) {
            MBARRIER_WAIT_PARITY(sb + 32 + st * 16, par);
            fill(cc + 2);
        }

        if (c == 3) {                    // epilogue for this item
            const int item = bid + (cc >> 2) * 148;
            const int nt = item >> 1, kh = item & 1;
            const int er = lane >> 2, ec = (lane & 3) * 2;
            const size_t nbase = (size_t)nt * 128 + wn * 64 + er;
            const int kbase = kh * 256 + wkq * 64 + ec;
#pragma unroll
            for (int mf = 0; mf < 4; ++mf) {
                const size_t r0 = nbase + mf * 16;
#pragma unroll
                for (int nf = 0; nf < 8; ++nf) {
                    const int col = kbase + nf * 8;
                    float* d = acc[mf][nf];
                    *(float2*)&out[r0 * KAT + col]       = make_float2(d[0], d[1]);
                    *(float2*)&out[(r0 + 8) * KAT + col] = make_float2(d[2], d[3]);
                }
            }
        }
    }
}

// ---------------------------------------------------------------------------
// Launch: 2 graph nodes, no allocations, deterministic, replay-safe.
// ---------------------------------------------------------------------------
extern "C" void kernel_launch(void* const* d_in, const int* in_sizes, int n_in,
                              void* d_out, int out_size) {
    (void)in_sizes; (void)n_in; (void)out_size;
    const float* z_e  = (const float*)d_in[0];   // [DIMD, NCOL]
    const float* dict = (const float*)d_in[1];   // [KAT, DIMD]
    float* out = (float*)d_out;                  // [NCOL, KAT]

    cudaFuncSetAttribute(prep_kernel,
                         cudaFuncAttributeMaxDynamicSharedMemorySize, SMEM_PREP);
    cudaFuncSetAttribute(out_mma_kernel,
                         cudaFuncAttributeMaxDynamicSharedMemorySize, SMEM_MMA);

    // 1) R15 prep with NDUAL=5 (one fewer dual pass; residual still below the
    //    drift floor), concurrent X->Aimg conversion on the other 84 SMs
    prep_kernel<<<NB + NCONV, 256, SMEM_PREP>>>(dict, z_e);

    // 2) persistent tensor-core GEMM, 64x64 warp tile (R15, unchanged)
    out_mma_kernel<<<148, 256, SMEM_MMA>>>(out);
}